// round 6
// baseline (speedup 1.0000x reference)
#include <cuda_runtime.h>
#include <cstdint>

// ---------------------------------------------------------------------------
// MultiHeadAttention block: Q/K/V proj -> softmax(QK^T/8) (full attn matrix is
// output #2) -> PV -> out proj + residual -> LayerNorm (output #1).
// fp32 throughout, packed fma.rn.f32x2 (Blackwell FFMA2) in all GEMM cores.
// ---------------------------------------------------------------------------

namespace {
constexpr int B  = 4;
constexpr int S  = 2048;
constexpr int D  = 512;
constexpr int H  = 8;
constexpr int DK = 64;
constexpr int DV = 64;
constexpr int BH = B * H;                       // 32
constexpr long long OUT_ELEMS  = (long long)B * S * D;          // 4,194,304
constexpr long long ATTN_ELEMS = (long long)B * H * S * S;      // 134,217,728
}

// Scratch (allocation-free rule: __device__ globals)
__device__ float g_Q[B * S * D];
__device__ float g_K[B * S * D];
__device__ float g_V[B * S * D];
__device__ float g_O[B * S * D];
__device__ float g_rowsum[BH * S];
__device__ float g_attn_fb[(size_t)BH * S * S];  // fallback if out buffer lacks attn

// ---- packed f32x2 helpers (FFMA2) -----------------------------------------
typedef unsigned long long u64;

__device__ __forceinline__ u64 dup2(float x) {
    u64 r; asm("mov.b64 %0, {%1,%2};" : "=l"(r) : "f"(x), "f"(x)); return r;
}
__device__ __forceinline__ void fma2(u64& c, u64 a, u64 b) {
    asm("fma.rn.f32x2 %0, %1, %2, %3;" : "=l"(c) : "l"(a), "l"(b), "l"(c));
}
__device__ __forceinline__ float2 unp2(u64 v) {
    float2 r; asm("mov.b64 {%0,%1}, %2;" : "=f"(r.x), "=f"(r.y) : "l"(v)); return r;
}

// ---------------------------------------------------------------------------
// Generic SGEMM: C = A(MxK) @ Bm(KxN) [+ R], all row-major. 128x128 tile,
// 256 threads, 8x8 per thread, BK=16.
// ---------------------------------------------------------------------------
template<bool RESID>
__global__ __launch_bounds__(256)
void sgemm_k(const float* __restrict__ A, const float* __restrict__ Bm,
             const float* __restrict__ R, float* __restrict__ C,
             int M, int N, int K)
{
    __shared__ float As[16][132];
    __shared__ float Bs[16][132];
    const int tid = threadIdx.x;
    const int m0 = blockIdx.y * 128, n0 = blockIdx.x * 128;
    const int tm = tid >> 4, tn = tid & 15;
    const int row0 = tm * 8, col0 = tn * 8;

    u64 acc[8][4];
#pragma unroll
    for (int i = 0; i < 8; i++)
#pragma unroll
        for (int j = 0; j < 4; j++) acc[i][j] = 0ULL;

    for (int k0 = 0; k0 < K; k0 += 16) {
#pragma unroll
        for (int r = 0; r < 2; r++) {
            int e = tid + r * 256;
            int ar = e >> 2, ac = (e & 3) << 2;
            const float4 v = *(const float4*)(A + (size_t)(m0 + ar) * K + k0 + ac);
            As[ac + 0][ar] = v.x; As[ac + 1][ar] = v.y;
            As[ac + 2][ar] = v.z; As[ac + 3][ar] = v.w;
        }
#pragma unroll
        for (int r = 0; r < 2; r++) {
            int e = tid + r * 256;
            int br = e >> 5, bc = (e & 31) << 2;
            *(float4*)&Bs[br][bc] =
                *(const float4*)(Bm + (size_t)(k0 + br) * N + n0 + bc);
        }
        __syncthreads();
#pragma unroll
        for (int kk = 0; kk < 16; kk++) {
            const float4 a0 = *(const float4*)&As[kk][row0];
            const float4 a1 = *(const float4*)&As[kk][row0 + 4];
            u64 ad[8] = {dup2(a0.x), dup2(a0.y), dup2(a0.z), dup2(a0.w),
                         dup2(a1.x), dup2(a1.y), dup2(a1.z), dup2(a1.w)};
            const u64* bp = (const u64*)&Bs[kk][col0];
            const u64 b0 = bp[0], b1 = bp[1], b2 = bp[2], b3 = bp[3];
#pragma unroll
            for (int i = 0; i < 8; i++) {
                fma2(acc[i][0], ad[i], b0);
                fma2(acc[i][1], ad[i], b1);
                fma2(acc[i][2], ad[i], b2);
                fma2(acc[i][3], ad[i], b3);
            }
        }
        __syncthreads();
    }

#pragma unroll
    for (int i = 0; i < 8; i++) {
        const size_t row = (size_t)m0 + row0 + i;
        float* cp = C + row * N + n0 + col0;
        float o[8];
#pragma unroll
        for (int j = 0; j < 4; j++) {
            float2 p = unp2(acc[i][j]); o[2 * j] = p.x; o[2 * j + 1] = p.y;
        }
        if (RESID) {
            const float* rp = R + row * N + n0 + col0;
            const float4 r0 = *(const float4*)rp, r1 = *(const float4*)(rp + 4);
            o[0] += r0.x; o[1] += r0.y; o[2] += r0.z; o[3] += r0.w;
            o[4] += r1.x; o[5] += r1.y; o[6] += r1.z; o[7] += r1.w;
        }
        *(float4*)cp       = make_float4(o[0], o[1], o[2], o[3]);
        *(float4*)(cp + 4) = make_float4(o[4], o[5], o[6], o[7]);
    }
}

// ---------------------------------------------------------------------------
// Scores: e = exp(mask ? -1e9 : QK^T/8) written unnormalized to attn buffer;
// per-row partial sums accumulated via atomicAdd. 128x128 tile per block.
// ---------------------------------------------------------------------------
__global__ __launch_bounds__(256)
void attn_scores_k(const float* __restrict__ Qp, const float* __restrict__ Kp,
                   const unsigned char* __restrict__ mask,
                   float* __restrict__ attn, float* __restrict__ rowsum)
{
    __shared__ float As[16][132];
    __shared__ float Bs[16][132];
    const int tid = threadIdx.x;
    const int bh = blockIdx.z, b = bh >> 3, h = bh & 7;
    const int q0 = blockIdx.y * 128, k0 = blockIdx.x * 128;
    const int tm = tid >> 4, tn = tid & 15;
    const int row0 = tm * 8, col0 = tn * 8;

    const float* Qb = Qp + ((size_t)b * S + q0) * D + h * DK;
    const float* Kb = Kp + ((size_t)b * S + k0) * D + h * DK;

    u64 acc[8][4];
#pragma unroll
    for (int i = 0; i < 8; i++)
#pragma unroll
        for (int j = 0; j < 4; j++) acc[i][j] = 0ULL;

    for (int kd = 0; kd < DK; kd += 16) {
#pragma unroll
        for (int r = 0; r < 2; r++) {
            int e = tid + r * 256;
            int ar = e >> 2, ac = (e & 3) << 2;
            const float4 v = *(const float4*)(Qb + (size_t)ar * D + kd + ac);
            As[ac + 0][ar] = v.x; As[ac + 1][ar] = v.y;
            As[ac + 2][ar] = v.z; As[ac + 3][ar] = v.w;
        }
#pragma unroll
        for (int r = 0; r < 2; r++) {
            int e = tid + r * 256;
            int kr = e >> 2, dc = (e & 3) << 2;
            const float4 v = *(const float4*)(Kb + (size_t)kr * D + kd + dc);
            Bs[dc + 0][kr] = v.x; Bs[dc + 1][kr] = v.y;
            Bs[dc + 2][kr] = v.z; Bs[dc + 3][kr] = v.w;
        }
        __syncthreads();
#pragma unroll
        for (int kk = 0; kk < 16; kk++) {
            const float4 a0 = *(const float4*)&As[kk][row0];
            const float4 a1 = *(const float4*)&As[kk][row0 + 4];
            u64 ad[8] = {dup2(a0.x), dup2(a0.y), dup2(a0.z), dup2(a0.w),
                         dup2(a1.x), dup2(a1.y), dup2(a1.z), dup2(a1.w)};
            const u64* bp = (const u64*)&Bs[kk][col0];
            const u64 b0 = bp[0], b1 = bp[1], b2 = bp[2], b3 = bp[3];
#pragma unroll
            for (int i = 0; i < 8; i++) {
                fma2(acc[i][0], ad[i], b0);
                fma2(acc[i][1], ad[i], b1);
                fma2(acc[i][2], ad[i], b2);
                fma2(acc[i][3], ad[i], b3);
            }
        }
        __syncthreads();
    }

    float rs[8];
#pragma unroll
    for (int i = 0; i < 8; i++) {
        const size_t q = (size_t)q0 + row0 + i;
        const u64 mraw = *(const u64*)(mask + ((size_t)b * S + q) * S + k0 + col0);
        float ev[8];
        float sum = 0.f;
#pragma unroll
        for (int j = 0; j < 4; j++) {
            float2 p = unp2(acc[i][j]);
            float s0 = p.x * 0.125f, s1 = p.y * 0.125f;
            if ((mraw >> (16 * j))     & 0xffULL) s0 = -1e9f;
            if ((mraw >> (16 * j + 8)) & 0xffULL) s1 = -1e9f;
            ev[2 * j]     = __expf(s0);
            ev[2 * j + 1] = __expf(s1);
            sum += ev[2 * j] + ev[2 * j + 1];
        }
        float* ap = attn + ((size_t)bh * S + q) * S + k0 + col0;
        *(float4*)ap       = make_float4(ev[0], ev[1], ev[2], ev[3]);
        *(float4*)(ap + 4) = make_float4(ev[4], ev[5], ev[6], ev[7]);
        rs[i] = sum;
    }
    // reduce within the 16-lane group sharing these 8 rows
#pragma unroll
    for (int i = 0; i < 8; i++) {
#pragma unroll
        for (int off = 8; off > 0; off >>= 1)
            rs[i] += __shfl_xor_sync(0xffffffffu, rs[i], off);
    }
    if (tn == 0) {
#pragma unroll
        for (int i = 0; i < 8; i++)
            atomicAdd(&rowsum[(size_t)bh * S + q0 + row0 + i], rs[i]);
    }
}

// ---------------------------------------------------------------------------
// Normalize attn in place (p = e / rowsum) and compute O = P @ V.
// Block owns 128 q-rows for one (b,h); loops full S in BK=32 chunks.
// ---------------------------------------------------------------------------
__global__ __launch_bounds__(256)
void attn_pv_k(float* __restrict__ attn, const float* __restrict__ Vp,
               const float* __restrict__ rowsum, float* __restrict__ O)
{
    __shared__ float Ps[32][132];
    __shared__ float Vs[32][68];
    __shared__ float ls[128];
    const int tid = threadIdx.x;
    const int bh = blockIdx.y, b = bh >> 3, h = bh & 7;
    const int q0 = blockIdx.x * 128;
    if (tid < 128) ls[tid] = 1.0f / rowsum[(size_t)bh * S + q0 + tid];
    __syncthreads();

    const int tm = tid >> 4, tn = tid & 15;
    const int row0 = tm * 8, col0 = tn * 4;
    float* Ab = attn + ((size_t)bh * S + q0) * S;
    const float* Vb = Vp + (size_t)b * S * D + h * DV;

    u64 acc[8][2];
#pragma unroll
    for (int i = 0; i < 8; i++) { acc[i][0] = 0ULL; acc[i][1] = 0ULL; }

    for (int kt = 0; kt < S; kt += 32) {
#pragma unroll
        for (int r = 0; r < 4; r++) {
            int e = tid + r * 256;
            int q = e >> 3, kc = (e & 7) << 2;
            float* gp = Ab + (size_t)q * S + kt + kc;
            float4 v = *(float4*)gp;
            const float rv = ls[q];
            v.x *= rv; v.y *= rv; v.z *= rv; v.w *= rv;
            *(float4*)gp = v;                       // final normalized attn
            Ps[kc + 0][q] = v.x; Ps[kc + 1][q] = v.y;
            Ps[kc + 2][q] = v.z; Ps[kc + 3][q] = v.w;
        }
#pragma unroll
        for (int r = 0; r < 2; r++) {
            int e = tid + r * 256;
            int k = e >> 4, dc = (e & 15) << 2;
            *(float4*)&Vs[k][dc] =
                *(const float4*)(Vb + (size_t)(kt + k) * D + dc);
        }
        __syncthreads();
#pragma unroll
        for (int kk = 0; kk < 32; kk++) {
            const float4 a0 = *(const float4*)&Ps[kk][row0];
            const float4 a1 = *(const float4*)&Ps[kk][row0 + 4];
            u64 ad[8] = {dup2(a0.x), dup2(a0.y), dup2(a0.z), dup2(a0.w),
                         dup2(a1.x), dup2(a1.y), dup2(a1.z), dup2(a1.w)};
            const u64* bp = (const u64*)&Vs[kk][col0];
            const u64 b0 = bp[0], b1 = bp[1];
#pragma unroll
            for (int i = 0; i < 8; i++) {
                fma2(acc[i][0], ad[i], b0);
                fma2(acc[i][1], ad[i], b1);
            }
        }
        __syncthreads();
    }
#pragma unroll
    for (int i = 0; i < 8; i++) {
        const float2 p0 = unp2(acc[i][0]), p1 = unp2(acc[i][1]);
        *(float4*)(O + ((size_t)b * S + q0 + row0 + i) * D + h * DV + col0) =
            make_float4(p0.x, p0.y, p1.x, p1.y);
    }
}

// ---------------------------------------------------------------------------
// Row LayerNorm: 1 block (128 threads) per row of 512.
// ---------------------------------------------------------------------------
__global__ __launch_bounds__(128)
void ln_k(const float* __restrict__ X, const float* __restrict__ gam,
          const float* __restrict__ bet, float* __restrict__ out)
{
    __shared__ float red[4];
    const int row = blockIdx.x, tid = threadIdx.x;
    const int lane = tid & 31, wid = tid >> 5;
    const float4 x = *(const float4*)(X + (size_t)row * D + tid * 4);

    float s = x.x + x.y + x.z + x.w;
#pragma unroll
    for (int off = 16; off > 0; off >>= 1) s += __shfl_xor_sync(~0u, s, off);
    if (lane == 0) red[wid] = s;
    __syncthreads();
    const float mu = (red[0] + red[1] + red[2] + red[3]) * (1.0f / D);
    __syncthreads();

    const float4 dx = make_float4(x.x - mu, x.y - mu, x.z - mu, x.w - mu);
    float q = dx.x * dx.x + dx.y * dx.y + dx.z * dx.z + dx.w * dx.w;
#pragma unroll
    for (int off = 16; off > 0; off >>= 1) q += __shfl_xor_sync(~0u, q, off);
    if (lane == 0) red[wid] = q;
    __syncthreads();
    const float var = (red[0] + red[1] + red[2] + red[3]) * (1.0f / D);
    const float inv = rsqrtf(var + 1e-5f);

    const float4 g  = *(const float4*)(gam + tid * 4);
    const float4 bb = *(const float4*)(bet + tid * 4);
    float4 y;
    y.x = dx.x * inv * g.x + bb.x;
    y.y = dx.y * inv * g.y + bb.y;
    y.z = dx.z * inv * g.z + bb.z;
    y.w = dx.w * inv * g.w + bb.w;
    *(float4*)(out + (size_t)row * D + tid * 4) = y;
}

// ---------------------------------------------------------------------------
extern "C" void kernel_launch(void* const* d_in, const int* in_sizes, int n_in,
                              void* d_out, int out_size)
{
    (void)in_sizes; (void)n_in;
    const float* Xq = (const float*)d_in[0];
    const float* Xk = (const float*)d_in[1];
    const float* Xv = (const float*)d_in[2];
    const unsigned char* mask = (const unsigned char*)d_in[3];
    const float* Wq = (const float*)d_in[4];
    const float* Wk = (const float*)d_in[5];
    const float* Wv = (const float*)d_in[6];
    const float* Wo = (const float*)d_in[7];
    const float* gam = (const float*)d_in[8];
    const float* bet = (const float*)d_in[9];
    float* out = (float*)d_out;

    float *gQ, *gK, *gV, *gO, *grs, *gfb;
    cudaGetSymbolAddress((void**)&gQ, g_Q);
    cudaGetSymbolAddress((void**)&gK, g_K);
    cudaGetSymbolAddress((void**)&gV, g_V);
    cudaGetSymbolAddress((void**)&gO, g_O);
    cudaGetSymbolAddress((void**)&grs, g_rowsum);
    cudaGetSymbolAddress((void**)&gfb, g_attn_fb);

    // tuple output flattening: [out (B,S,D), attn (B,H,S,S)]
    float* attnp = ((long long)out_size >= OUT_ELEMS + ATTN_ELEMS)
                       ? (out + OUT_ELEMS) : gfb;

    const dim3 gproj(D / 128, (B * S) / 128);      // (4, 64)
    sgemm_k<false><<<gproj, 256>>>(Xq, Wq, nullptr, gQ, B * S, D, D);
    sgemm_k<false><<<gproj, 256>>>(Xk, Wk, nullptr, gK, B * S, D, D);
    sgemm_k<false><<<gproj, 256>>>(Xv, Wv, nullptr, gV, B * S, D, D);

    cudaMemsetAsync(grs, 0, sizeof(float) * BH * S);
    attn_scores_k<<<dim3(S / 128, S / 128, BH), 256>>>(gQ, gK, mask, attnp, grs);
    attn_pv_k<<<dim3(S / 128, BH), 256>>>(attnp, gV, grs, gO);

    // out proj + residual (reuse gK as Y scratch), then LayerNorm
    sgemm_k<true><<<gproj, 256>>>(gO, Wo, Xq, gK, B * S, D, D);
    ln_k<<<B * S, 128>>>(gK, gam, bet, out);
}

// round 7
// speedup vs baseline: 1.0001x; 1.0001x over previous
#include <cuda_runtime.h>
#include <cstdint>

// ---------------------------------------------------------------------------
// MultiHeadAttention block: Q/K/V proj -> softmax(QK^T/8) (full attn matrix is
// output #2) -> PV -> out proj + residual -> LayerNorm (output #1).
// fp32 throughout, packed fma.rn.f32x2 (Blackwell FFMA2) in all GEMM cores.
// ---------------------------------------------------------------------------

namespace {
constexpr int B  = 4;
constexpr int S  = 2048;
constexpr int D  = 512;
constexpr int H  = 8;
constexpr int DK = 64;
constexpr int DV = 64;
constexpr int BH = B * H;                       // 32
constexpr long long OUT_ELEMS  = (long long)B * S * D;          // 4,194,304
constexpr long long ATTN_ELEMS = (long long)B * H * S * S;      // 134,217,728
}

// Scratch (allocation-free rule: __device__ globals)
__device__ float g_Q[B * S * D];
__device__ float g_K[B * S * D];
__device__ float g_V[B * S * D];
__device__ float g_O[B * S * D];
__device__ float g_rowsum[BH * S];
__device__ float g_attn_fb[(size_t)BH * S * S];  // fallback if out buffer lacks attn

// ---- packed f32x2 helpers (FFMA2) -----------------------------------------
typedef unsigned long long u64;

__device__ __forceinline__ u64 dup2(float x) {
    u64 r; asm("mov.b64 %0, {%1,%2};" : "=l"(r) : "f"(x), "f"(x)); return r;
}
__device__ __forceinline__ void fma2(u64& c, u64 a, u64 b) {
    asm("fma.rn.f32x2 %0, %1, %2, %3;" : "=l"(c) : "l"(a), "l"(b), "l"(c));
}
__device__ __forceinline__ float2 unp2(u64 v) {
    float2 r; asm("mov.b64 {%0,%1}, %2;" : "=f"(r.x), "=f"(r.y) : "l"(v)); return r;
}

// ---------------------------------------------------------------------------
// Generic SGEMM: C = A(MxK) @ Bm(KxN) [+ R], all row-major. 128x128 tile,
// 256 threads, 8x8 per thread, BK=16.
// ---------------------------------------------------------------------------
template<bool RESID>
__global__ __launch_bounds__(256)
void sgemm_k(const float* __restrict__ A, const float* __restrict__ Bm,
             const float* __restrict__ R, float* __restrict__ C,
             int M, int N, int K)
{
    __shared__ float As[16][132];
    __shared__ float Bs[16][132];
    const int tid = threadIdx.x;
    const int m0 = blockIdx.y * 128, n0 = blockIdx.x * 128;
    const int tm = tid >> 4, tn = tid & 15;
    const int row0 = tm * 8, col0 = tn * 8;

    u64 acc[8][4];
#pragma unroll
    for (int i = 0; i < 8; i++)
#pragma unroll
        for (int j = 0; j < 4; j++) acc[i][j] = 0ULL;

    for (int k0 = 0; k0 < K; k0 += 16) {
#pragma unroll
        for (int r = 0; r < 2; r++) {
            int e = tid + r * 256;
            int ar = e >> 2, ac = (e & 3) << 2;
            const float4 v = *(const float4*)(A + (size_t)(m0 + ar) * K + k0 + ac);
            As[ac + 0][ar] = v.x; As[ac + 1][ar] = v.y;
            As[ac + 2][ar] = v.z; As[ac + 3][ar] = v.w;
        }
#pragma unroll
        for (int r = 0; r < 2; r++) {
            int e = tid + r * 256;
            int br = e >> 5, bc = (e & 31) << 2;
            *(float4*)&Bs[br][bc] =
                *(const float4*)(Bm + (size_t)(k0 + br) * N + n0 + bc);
        }
        __syncthreads();
#pragma unroll
        for (int kk = 0; kk < 16; kk++) {
            const float4 a0 = *(const float4*)&As[kk][row0];
            const float4 a1 = *(const float4*)&As[kk][row0 + 4];
            u64 ad[8] = {dup2(a0.x), dup2(a0.y), dup2(a0.z), dup2(a0.w),
                         dup2(a1.x), dup2(a1.y), dup2(a1.z), dup2(a1.w)};
            const u64* bp = (const u64*)&Bs[kk][col0];
            const u64 b0 = bp[0], b1 = bp[1], b2 = bp[2], b3 = bp[3];
#pragma unroll
            for (int i = 0; i < 8; i++) {
                fma2(acc[i][0], ad[i], b0);
                fma2(acc[i][1], ad[i], b1);
                fma2(acc[i][2], ad[i], b2);
                fma2(acc[i][3], ad[i], b3);
            }
        }
        __syncthreads();
    }

#pragma unroll
    for (int i = 0; i < 8; i++) {
        const size_t row = (size_t)m0 + row0 + i;
        float* cp = C + row * N + n0 + col0;
        float o[8];
#pragma unroll
        for (int j = 0; j < 4; j++) {
            float2 p = unp2(acc[i][j]); o[2 * j] = p.x; o[2 * j + 1] = p.y;
        }
        if (RESID) {
            const float* rp = R + row * N + n0 + col0;
            const float4 r0 = *(const float4*)rp, r1 = *(const float4*)(rp + 4);
            o[0] += r0.x; o[1] += r0.y; o[2] += r0.z; o[3] += r0.w;
            o[4] += r1.x; o[5] += r1.y; o[6] += r1.z; o[7] += r1.w;
        }
        *(float4*)cp       = make_float4(o[0], o[1], o[2], o[3]);
        *(float4*)(cp + 4) = make_float4(o[4], o[5], o[6], o[7]);
    }
}

// ---------------------------------------------------------------------------
// Scores: e = exp(mask ? -1e9 : QK^T/8) written unnormalized to attn buffer;
// per-row partial sums accumulated via atomicAdd. 128x128 tile per block.
// ---------------------------------------------------------------------------
__global__ __launch_bounds__(256)
void attn_scores_k(const float* __restrict__ Qp, const float* __restrict__ Kp,
                   const unsigned char* __restrict__ mask,
                   float* __restrict__ attn, float* __restrict__ rowsum)
{
    __shared__ float As[16][132];
    __shared__ float Bs[16][132];
    const int tid = threadIdx.x;
    const int bh = blockIdx.z, b = bh >> 3, h = bh & 7;
    const int q0 = blockIdx.y * 128, k0 = blockIdx.x * 128;
    const int tm = tid >> 4, tn = tid & 15;
    const int row0 = tm * 8, col0 = tn * 8;

    const float* Qb = Qp + ((size_t)b * S + q0) * D + h * DK;
    const float* Kb = Kp + ((size_t)b * S + k0) * D + h * DK;

    u64 acc[8][4];
#pragma unroll
    for (int i = 0; i < 8; i++)
#pragma unroll
        for (int j = 0; j < 4; j++) acc[i][j] = 0ULL;

    for (int kd = 0; kd < DK; kd += 16) {
#pragma unroll
        for (int r = 0; r < 2; r++) {
            int e = tid + r * 256;
            int ar = e >> 2, ac = (e & 3) << 2;
            const float4 v = *(const float4*)(Qb + (size_t)ar * D + kd + ac);
            As[ac + 0][ar] = v.x; As[ac + 1][ar] = v.y;
            As[ac + 2][ar] = v.z; As[ac + 3][ar] = v.w;
        }
#pragma unroll
        for (int r = 0; r < 2; r++) {
            int e = tid + r * 256;
            int kr = e >> 2, dc = (e & 3) << 2;
            const float4 v = *(const float4*)(Kb + (size_t)kr * D + kd + dc);
            Bs[dc + 0][kr] = v.x; Bs[dc + 1][kr] = v.y;
            Bs[dc + 2][kr] = v.z; Bs[dc + 3][kr] = v.w;
        }
        __syncthreads();
#pragma unroll
        for (int kk = 0; kk < 16; kk++) {
            const float4 a0 = *(const float4*)&As[kk][row0];
            const float4 a1 = *(const float4*)&As[kk][row0 + 4];
            u64 ad[8] = {dup2(a0.x), dup2(a0.y), dup2(a0.z), dup2(a0.w),
                         dup2(a1.x), dup2(a1.y), dup2(a1.z), dup2(a1.w)};
            const u64* bp = (const u64*)&Bs[kk][col0];
            const u64 b0 = bp[0], b1 = bp[1], b2 = bp[2], b3 = bp[3];
#pragma unroll
            for (int i = 0; i < 8; i++) {
                fma2(acc[i][0], ad[i], b0);
                fma2(acc[i][1], ad[i], b1);
                fma2(acc[i][2], ad[i], b2);
                fma2(acc[i][3], ad[i], b3);
            }
        }
        __syncthreads();
    }

    float rs[8];
#pragma unroll
    for (int i = 0; i < 8; i++) {
        const size_t q = (size_t)q0 + row0 + i;
        const u64 mraw = *(const u64*)(mask + ((size_t)b * S + q) * S + k0 + col0);
        float ev[8];
        float sum = 0.f;
#pragma unroll
        for (int j = 0; j < 4; j++) {
            float2 p = unp2(acc[i][j]);
            float s0 = p.x * 0.125f, s1 = p.y * 0.125f;
            if ((mraw >> (16 * j))     & 0xffULL) s0 = -1e9f;
            if ((mraw >> (16 * j + 8)) & 0xffULL) s1 = -1e9f;
            ev[2 * j]     = __expf(s0);
            ev[2 * j + 1] = __expf(s1);
            sum += ev[2 * j] + ev[2 * j + 1];
        }
        float* ap = attn + ((size_t)bh * S + q) * S + k0 + col0;
        *(float4*)ap       = make_float4(ev[0], ev[1], ev[2], ev[3]);
        *(float4*)(ap + 4) = make_float4(ev[4], ev[5], ev[6], ev[7]);
        rs[i] = sum;
    }
    // reduce within the 16-lane group sharing these 8 rows
#pragma unroll
    for (int i = 0; i < 8; i++) {
#pragma unroll
        for (int off = 8; off > 0; off >>= 1)
            rs[i] += __shfl_xor_sync(0xffffffffu, rs[i], off);
    }
    if (tn == 0) {
#pragma unroll
        for (int i = 0; i < 8; i++)
            atomicAdd(&rowsum[(size_t)bh * S + q0 + row0 + i], rs[i]);
    }
}

// ---------------------------------------------------------------------------
// Normalize attn in place (p = e / rowsum) and compute O = P @ V.
// Block owns 128 q-rows for one (b,h); loops full S in BK=32 chunks.
// ---------------------------------------------------------------------------
__global__ __launch_bounds__(256)
void attn_pv_k(float* __restrict__ attn, const float* __restrict__ Vp,
               const float* __restrict__ rowsum, float* __restrict__ O)
{
    __shared__ float Ps[32][132];
    __shared__ float Vs[32][68];
    __shared__ float ls[128];
    const int tid = threadIdx.x;
    const int bh = blockIdx.y, b = bh >> 3, h = bh & 7;
    const int q0 = blockIdx.x * 128;
    if (tid < 128) ls[tid] = 1.0f / rowsum[(size_t)bh * S + q0 + tid];
    __syncthreads();

    const int tm = tid >> 4, tn = tid & 15;
    const int row0 = tm * 8, col0 = tn * 4;
    float* Ab = attn + ((size_t)bh * S + q0) * S;
    const float* Vb = Vp + (size_t)b * S * D + h * DV;

    u64 acc[8][2];
#pragma unroll
    for (int i = 0; i < 8; i++) { acc[i][0] = 0ULL; acc[i][1] = 0ULL; }

    for (int kt = 0; kt < S; kt += 32) {
#pragma unroll
        for (int r = 0; r < 4; r++) {
            int e = tid + r * 256;
            int q = e >> 3, kc = (e & 7) << 2;
            float* gp = Ab + (size_t)q * S + kt + kc;
            float4 v = *(float4*)gp;
            const float rv = ls[q];
            v.x *= rv; v.y *= rv; v.z *= rv; v.w *= rv;
            *(float4*)gp = v;                       // final normalized attn
            Ps[kc + 0][q] = v.x; Ps[kc + 1][q] = v.y;
            Ps[kc + 2][q] = v.z; Ps[kc + 3][q] = v.w;
        }
#pragma unroll
        for (int r = 0; r < 2; r++) {
            int e = tid + r * 256;
            int k = e >> 4, dc = (e & 15) << 2;
            *(float4*)&Vs[k][dc] =
                *(const float4*)(Vb + (size_t)(kt + k) * D + dc);
        }
        __syncthreads();
#pragma unroll
        for (int kk = 0; kk < 32; kk++) {
            const float4 a0 = *(const float4*)&Ps[kk][row0];
            const float4 a1 = *(const float4*)&Ps[kk][row0 + 4];
            u64 ad[8] = {dup2(a0.x), dup2(a0.y), dup2(a0.z), dup2(a0.w),
                         dup2(a1.x), dup2(a1.y), dup2(a1.z), dup2(a1.w)};
            const u64* bp = (const u64*)&Vs[kk][col0];
            const u64 b0 = bp[0], b1 = bp[1];
#pragma unroll
            for (int i = 0; i < 8; i++) {
                fma2(acc[i][0], ad[i], b0);
                fma2(acc[i][1], ad[i], b1);
            }
        }
        __syncthreads();
    }
#pragma unroll
    for (int i = 0; i < 8; i++) {
        const float2 p0 = unp2(acc[i][0]), p1 = unp2(acc[i][1]);
        *(float4*)(O + ((size_t)b * S + q0 + row0 + i) * D + h * DV + col0) =
            make_float4(p0.x, p0.y, p1.x, p1.y);
    }
}

// ---------------------------------------------------------------------------
// Row LayerNorm: 1 block (128 threads) per row of 512.
// ---------------------------------------------------------------------------
__global__ __launch_bounds__(128)
void ln_k(const float* __restrict__ X, const float* __restrict__ gam,
          const float* __restrict__ bet, float* __restrict__ out)
{
    __shared__ float red[4];
    const int row = blockIdx.x, tid = threadIdx.x;
    const int lane = tid & 31, wid = tid >> 5;
    const float4 x = *(const float4*)(X + (size_t)row * D + tid * 4);

    float s = x.x + x.y + x.z + x.w;
#pragma unroll
    for (int off = 16; off > 0; off >>= 1) s += __shfl_xor_sync(~0u, s, off);
    if (lane == 0) red[wid] = s;
    __syncthreads();
    const float mu = (red[0] + red[1] + red[2] + red[3]) * (1.0f / D);
    __syncthreads();

    const float4 dx = make_float4(x.x - mu, x.y - mu, x.z - mu, x.w - mu);
    float q = dx.x * dx.x + dx.y * dx.y + dx.z * dx.z + dx.w * dx.w;
#pragma unroll
    for (int off = 16; off > 0; off >>= 1) q += __shfl_xor_sync(~0u, q, off);
    if (lane == 0) red[wid] = q;
    __syncthreads();
    const float var = (red[0] + red[1] + red[2] + red[3]) * (1.0f / D);
    const float inv = rsqrtf(var + 1e-5f);

    const float4 g  = *(const float4*)(gam + tid * 4);
    const float4 bb = *(const float4*)(bet + tid * 4);
    float4 y;
    y.x = dx.x * inv * g.x + bb.x;
    y.y = dx.y * inv * g.y + bb.y;
    y.z = dx.z * inv * g.z + bb.z;
    y.w = dx.w * inv * g.w + bb.w;
    *(float4*)(out + (size_t)row * D + tid * 4) = y;
}

// ---------------------------------------------------------------------------
extern "C" void kernel_launch(void* const* d_in, const int* in_sizes, int n_in,
                              void* d_out, int out_size)
{
    (void)in_sizes; (void)n_in;
    const float* Xq = (const float*)d_in[0];
    const float* Xk = (const float*)d_in[1];
    const float* Xv = (const float*)d_in[2];
    const unsigned char* mask = (const unsigned char*)d_in[3];
    const float* Wq = (const float*)d_in[4];
    const float* Wk = (const float*)d_in[5];
    const float* Wv = (const float*)d_in[6];
    const float* Wo = (const float*)d_in[7];
    const float* gam = (const float*)d_in[8];
    const float* bet = (const float*)d_in[9];
    float* out = (float*)d_out;

    float *gQ, *gK, *gV, *gO, *grs, *gfb;
    cudaGetSymbolAddress((void**)&gQ, g_Q);
    cudaGetSymbolAddress((void**)&gK, g_K);
    cudaGetSymbolAddress((void**)&gV, g_V);
    cudaGetSymbolAddress((void**)&gO, g_O);
    cudaGetSymbolAddress((void**)&grs, g_rowsum);
    cudaGetSymbolAddress((void**)&gfb, g_attn_fb);

    // tuple output flattening: [out (B,S,D), attn (B,H,S,S)]
    float* attnp = ((long long)out_size >= OUT_ELEMS + ATTN_ELEMS)
                       ? (out + OUT_ELEMS) : gfb;

    const dim3 gproj(D / 128, (B * S) / 128);      // (4, 64)
    sgemm_k<false><<<gproj, 256>>>(Xq, Wq, nullptr, gQ, B * S, D, D);
    sgemm_k<false><<<gproj, 256>>>(Xk, Wk, nullptr, gK, B * S, D, D);
    sgemm_k<false><<<gproj, 256>>>(Xv, Wv, nullptr, gV, B * S, D, D);

    cudaMemsetAsync(grs, 0, sizeof(float) * BH * S);
    attn_scores_k<<<dim3(S / 128, S / 128, BH), 256>>>(gQ, gK, mask, attnp, grs);
    attn_pv_k<<<dim3(S / 128, BH), 256>>>(attnp, gV, grs, gO);

    // out proj + residual (reuse gK as Y scratch), then LayerNorm
    sgemm_k<true><<<gproj, 256>>>(gO, Wo, Xq, gK, B * S, D, D);
    ln_k<<<B * S, 128>>>(gK, gam, bet, out);
}